// round 2
// baseline (speedup 1.0000x reference)
#include <cuda_runtime.h>

// SurfNetwork: grid-feature gather + tiny color MLP + volume rendering.
// One warp per ray (b). Lane L handles samples n = 4L .. 4L+3 (contiguous,
// so the transmittance cumprod factorizes into per-lane products + a warp
// exclusive product scan).
//
// Inputs (metadata order):
//   d_in[0] x          int32  [B, N, 2]    gather indices
//   d_in[1] d          f32    [B, 16]      view direction features
//   d_in[2] gridWeight f32    [16777216,4] feature table (256 MB)
//   d_in[3] W0         f32    [22, 8]
//   d_in[4] W1         f32    [8, 3]
// Output: concat(sigma[B*N], rgb[B*3]) as f32.

#define RAY_N 128

__global__ __launch_bounds__(256) void surf_kernel(
    const int*    __restrict__ x,
    const float*  __restrict__ dvec,
    const float4* __restrict__ gw,
    const float*  __restrict__ W0,
    const float*  __restrict__ W1,
    float*        __restrict__ sigma_out,
    float*        __restrict__ rgb_out,
    int B)
{
    __shared__ float sW0[22 * 8];
    __shared__ float sW1[8 * 3];
    int tid = threadIdx.x;
    if (tid < 176) sW0[tid] = W0[tid];
    if (tid < 24)  sW1[tid] = W1[tid];
    __syncthreads();

    int warp = (int)((blockIdx.x * blockDim.x + tid) >> 5);
    if (warp >= B) return;
    int lane = tid & 31;

    // ---- index load: 8 consecutive ints per lane (2 x int4, coalesced) ----
    const int4* xr = (const int4*)(x + (size_t)warp * (RAY_N * 2));
    int4 xa = __ldg(&xr[lane * 2]);
    int4 xb = __ldg(&xr[lane * 2 + 1]);

    // d: one coalesced float per lane (lanes 0..15), broadcast later.
    const float* dr = dvec + (size_t)warp * 16;
    float dmine = __ldg(&dr[lane & 15]);

    // ---- issue all 8 random gathers up front (max MLP) ----
    float4 f0 = __ldg(&gw[xa.x]);
    float4 f1 = __ldg(&gw[xa.y]);
    float4 f2 = __ldg(&gw[xa.z]);
    float4 f3 = __ldg(&gw[xa.w]);
    float4 f4 = __ldg(&gw[xb.x]);
    float4 f5 = __ldg(&gw[xb.y]);
    float4 f6 = __ldg(&gw[xb.z]);
    float4 f7 = __ldg(&gw[xb.w]);

    // ---- per-ray direction part of layer 0: base[k] = sum_i d[i]*W0[i][k] ----
    float base[8];
    #pragma unroll
    for (int k = 0; k < 8; k++) base[k] = 0.f;
    #pragma unroll
    for (int i = 0; i < 16; i++) {
        float dv = __shfl_sync(0xffffffffu, dmine, i);
        #pragma unroll
        for (int k = 0; k < 8; k++)
            base[k] = fmaf(dv, sW0[i * 8 + k], base[k]);
    }

    float sig[4];
    float acc0 = 0.f, acc1 = 0.f, acc2 = 0.f;
    float Tloc = 1.f;

    #pragma unroll
    for (int s = 0; s < 4; s++) {
        float4 a = (s == 0) ? f0 : (s == 1) ? f2 : (s == 2) ? f4 : f6;
        float4 b = (s == 0) ? f1 : (s == 1) ? f3 : (s == 2) ? f5 : f7;

        float sg = 1.f / (1.f + __expf(-(a.x * b.x)));
        sig[s] = sg;

        // geo part of layer 0 + ReLU
        float h[8];
        #pragma unroll
        for (int k = 0; k < 8; k++) {
            float v = base[k];
            v = fmaf(a.y, sW0[16 * 8 + k], v);
            v = fmaf(a.z, sW0[17 * 8 + k], v);
            v = fmaf(a.w, sW0[18 * 8 + k], v);
            v = fmaf(b.y, sW0[19 * 8 + k], v);
            v = fmaf(b.z, sW0[20 * 8 + k], v);
            v = fmaf(b.w, sW0[21 * 8 + k], v);
            h[k] = fmaxf(v, 0.f);
        }

        // layer 1 + sigmoid
        float z0 = 0.f, z1 = 0.f, z2 = 0.f;
        #pragma unroll
        for (int k = 0; k < 8; k++) {
            z0 = fmaf(h[k], sW1[k * 3 + 0], z0);
            z1 = fmaf(h[k], sW1[k * 3 + 1], z1);
            z2 = fmaf(h[k], sW1[k * 3 + 2], z2);
        }
        float c0 = 1.f / (1.f + __expf(-z0));
        float c1 = 1.f / (1.f + __expf(-z1));
        float c2 = 1.f / (1.f + __expf(-z2));

        // local (within-lane) transmittance chain
        float w = Tloc * sg;
        acc0 = fmaf(w, c0, acc0);
        acc1 = fmaf(w, c1, acc1);
        acc2 = fmaf(w, c2, acc2);
        Tloc *= (1.f - sg);
    }

    // ---- warp exclusive product scan of per-lane (1-sigma) products ----
    float sp = Tloc;
    #pragma unroll
    for (int off = 1; off < 32; off <<= 1) {
        float v = __shfl_up_sync(0xffffffffu, sp, off);
        sp *= (lane >= off) ? v : 1.f;     // select, no divergent branch
    }
    float Tpre = __shfl_up_sync(0xffffffffu, sp, 1);
    Tpre = (lane == 0) ? 1.f : Tpre;

    acc0 *= Tpre; acc1 *= Tpre; acc2 *= Tpre;

    // ---- warp reduce rgb ----
    #pragma unroll
    for (int off = 16; off >= 1; off >>= 1) {
        acc0 += __shfl_down_sync(0xffffffffu, acc0, off);
        acc1 += __shfl_down_sync(0xffffffffu, acc1, off);
        acc2 += __shfl_down_sync(0xffffffffu, acc2, off);
    }

    // ---- stores ----
    ((float4*)(sigma_out + (size_t)warp * RAY_N))[lane] =
        make_float4(sig[0], sig[1], sig[2], sig[3]);
    if (lane == 0) {
        float* r = rgb_out + (size_t)warp * 3;
        r[0] = acc0; r[1] = acc1; r[2] = acc2;
    }
}

extern "C" void kernel_launch(void* const* d_in, const int* in_sizes, int n_in,
                              void* d_out, int out_size)
{
    const int*    x    = (const int*)d_in[0];
    const float*  dvec = (const float*)d_in[1];
    const float4* gw   = (const float4*)d_in[2];
    const float*  W0   = (const float*)d_in[3];
    const float*  W1   = (const float*)d_in[4];

    int B = in_sizes[1] / 16;                 // d is [B, 16]
    float* out   = (float*)d_out;
    float* sigma = out;                        // [B, 128]
    float* rgb   = out + (size_t)B * RAY_N;    // [B, 3]

    const int warpsPerBlock = 8;               // 256 threads
    int blocks = (B + warpsPerBlock - 1) / warpsPerBlock;
    surf_kernel<<<blocks, 256>>>(x, dvec, gw, W0, W1, sigma, rgb, B);
}